// round 16
// baseline (speedup 1.0000x reference)
#include <cuda_runtime.h>
#include <cuda_bf16.h>
#include <cstdint>
#include <math.h>

// Problem constants
#define B_SZ   1024
#define T_SZ   4
#define D_IN_  768
#define D_SAE_ 8192
#define KTOP   32
#define KCAND  40          // minimum candidate count (superset size target)
#define NCAP   96          // candidate hard cap
#define KDIM   3072        // T*D_IN

// ---------------- static device scratch (no allocs) ----------------
__device__ __align__(1024) float         g_Wt_f32[(size_t)D_SAE_ * KDIM];   // W_enc^T fp32 (exact rescore)
__device__ __align__(1024) __nv_bfloat16 g_Wt_bf16[(size_t)D_SAE_ * KDIM];  // W_enc^T bf16 (MMA B)
__device__ __align__(1024) __nv_bfloat16 g_x_bf16[(size_t)B_SZ * KDIM];     // x bf16 (MMA A)
__device__ __align__(1024) __nv_bfloat16 g_pre[(size_t)B_SZ * D_SAE_];      // approx pre (bf16)
__device__ int   g_cand[B_SZ * NCAP];
__device__ int   g_cand_n[B_SZ];
__device__ float g_loss_partial[B_SZ];

// ---------------- PTX helpers (base ISA only: sm_80+) ----------------
__device__ __forceinline__ uint32_t smem_u32(const void* p) {
    uint32_t r;
    asm("{ .reg .u64 t; cvta.to.shared.u64 t, %1; cvt.u32.u64 %0, t; }" : "=r"(r) : "l"(p));
    return r;
}

__device__ __forceinline__ void cp_async16(uint32_t dst, const void* src) {
    asm volatile("cp.async.cg.shared.global [%0], [%1], 16;" :: "r"(dst), "l"(src));
}
#define CP_COMMIT() asm volatile("cp.async.commit_group;" ::: "memory")
#define CP_WAIT0()  asm volatile("cp.async.wait_group 0;" ::: "memory")
#define CP_WAIT1()  asm volatile("cp.async.wait_group 1;" ::: "memory")

__device__ __forceinline__ void ldsm_x4(uint32_t& r0, uint32_t& r1, uint32_t& r2, uint32_t& r3,
                                        uint32_t addr) {
    asm volatile("ldmatrix.sync.aligned.m8n8.x4.shared.b16 {%0,%1,%2,%3}, [%4];"
                 : "=r"(r0), "=r"(r1), "=r"(r2), "=r"(r3) : "r"(addr));
}

__device__ __forceinline__ void mma16816(float* c, const uint32_t* a, uint32_t b0, uint32_t b1) {
    asm volatile(
        "mma.sync.aligned.m16n8k16.row.col.f32.bf16.bf16.f32 "
        "{%0,%1,%2,%3}, {%4,%5,%6,%7}, {%8,%9}, {%0,%1,%2,%3};"
        : "+f"(c[0]), "+f"(c[1]), "+f"(c[2]), "+f"(c[3])
        : "r"(a[0]), "r"(a[1]), "r"(a[2]), "r"(a[3]), "r"(b0), "r"(b1));
}

// monotonic bf16-bits -> 16-bit key (total order preserved)
__device__ __forceinline__ uint32_t fkey16(uint32_t h) {
    return (h & 0x8000u) ? (~h & 0xFFFFu) : (h | 0x8000u);
}

// =====================================================================
// Kernel A: x fp32 -> bf16
// =====================================================================
__global__ __launch_bounds__(256) void convert_x_kernel(const float* __restrict__ x)
{
    int i = blockIdx.x * 256 + threadIdx.x;          // over 786432 float4s
    float4 v = ((const float4*)x)[i];
    __nv_bfloat162* o = (__nv_bfloat162*)g_x_bf16;
    o[i * 2 + 0] = __nv_bfloat162(__float2bfloat16_rn(v.x), __float2bfloat16_rn(v.y));
    o[i * 2 + 1] = __nv_bfloat162(__float2bfloat16_rn(v.z), __float2bfloat16_rn(v.w));
}

// =====================================================================
// Kernel B: transpose W_enc (3072,8192) -> Wt (8192,3072) fp32 + bf16
// =====================================================================
__global__ __launch_bounds__(256) void transpose_w_kernel(const float* __restrict__ W)
{
    __shared__ float s[32][129];
    const int k0 = blockIdx.x * 32;
    const int n0 = blockIdx.y * 128;
    const int t = threadIdx.x;

    {
        const int rr = t >> 5;
        const int c4 = t & 31;
        #pragma unroll
        for (int p = 0; p < 4; ++p) {
            const int kr = p * 8 + rr;
            float4 v = *(const float4*)&W[(size_t)(k0 + kr) * D_SAE_ + n0 + c4 * 4];
            s[kr][c4 * 4 + 0] = v.x;
            s[kr][c4 * 4 + 1] = v.y;
            s[kr][c4 * 4 + 2] = v.z;
            s[kr][c4 * 4 + 3] = v.w;
        }
    }
    __syncthreads();

    {
        const int nr = t >> 1;
        const int kb = (t & 1) * 16;
        float vals[16];
        #pragma unroll
        for (int i = 0; i < 16; ++i) vals[i] = s[kb + i][nr];

        float* wf = g_Wt_f32 + (size_t)(n0 + nr) * KDIM + k0 + kb;
        #pragma unroll
        for (int i4 = 0; i4 < 4; ++i4)
            *(float4*)(wf + i4 * 4) =
                make_float4(vals[i4 * 4], vals[i4 * 4 + 1], vals[i4 * 4 + 2], vals[i4 * 4 + 3]);

        __nv_bfloat162 bb[8];
        #pragma unroll
        for (int i = 0; i < 8; ++i)
            bb[i] = __nv_bfloat162(__float2bfloat16_rn(vals[i * 2]),
                                   __float2bfloat16_rn(vals[i * 2 + 1]));
        uint4* wb = (uint4*)(g_Wt_bf16 + (size_t)(n0 + nr) * KDIM + k0 + kb);
        wb[0] = *(uint4*)&bb[0];
        wb[1] = *(uint4*)&bb[4];
    }
}

// =====================================================================
// Kernel C: bf16 HMMA GEMM  g_pre(bf16) = x_bf16 @ Wt_bf16^T + b_enc
// CTA 128x128, 8 warps (2x4), warp tile 64x32. K-chunk 64, NSTG=3,
// wait->sync->issue pipeline, 2 CTAs/SM. (round-8 proven config)
// =====================================================================
#define BKT  64
#define NIT  (KDIM / BKT)      // 48
#define ROWP 72                // padded row length in bf16 elems (144 B rows)
#define STAGE_B (128 * ROWP * 2)   // 18432 bytes per operand per stage
#define NSTG 3
#define GSMEM   (2 * NSTG * STAGE_B)   // 110592 bytes

__global__ __launch_bounds__(256, 2) void encode_gemm_hmma(const float* __restrict__ b_enc)
{
    extern __shared__ __nv_bfloat16 smdyn[];

    const int tid  = threadIdx.x;
    const int wid  = tid >> 5, lane = tid & 31;
    const int m0 = blockIdx.x * 128;     // m fastest
    const int n0 = blockIdx.y * 128;
    const int wm = (wid >> 2) * 64;
    const int wn = (wid & 3) * 32;

    const uint32_t smb = smem_u32(smdyn);
    const __nv_bfloat16* __restrict__ Abf = g_x_bf16;
    const __nv_bfloat16* __restrict__ Bbf = g_Wt_bf16;

    #define ISSUE(itc, st) do {                                                           \
        int _k0 = (itc) * BKT;                                                            \
        uint32_t _ab = smb + (uint32_t)(st) * STAGE_B;                                    \
        uint32_t _bb = smb + (uint32_t)(NSTG + (st)) * STAGE_B;                           \
        _Pragma("unroll")                                                                 \
        for (int q = 0; q < 4; ++q) {                                                     \
            int u = tid + q * 256, row = u >> 3, seg = u & 7;                             \
            uint32_t doff = (uint32_t)(row * ROWP + seg * 8) * 2;                         \
            cp_async16(_ab + doff, Abf + (size_t)(m0 + row) * KDIM + _k0 + seg * 8);      \
            cp_async16(_bb + doff, Bbf + (size_t)(n0 + row) * KDIM + _k0 + seg * 8);      \
        }                                                                                 \
        CP_COMMIT();                                                                      \
    } while (0)

    float c[4][4][4];
    #pragma unroll
    for (int i = 0; i < 4; ++i)
        #pragma unroll
        for (int j = 0; j < 4; ++j)
            #pragma unroll
            for (int q = 0; q < 4; ++q) c[i][j][q] = 0.0f;

    ISSUE(0, 0);
    ISSUE(1, 1);

    const int a_row = wm + (lane & 15);
    const int a_kh  = (lane >> 4) * 8;
    const int b_r   = lane & 7;
    const int b_grp = lane >> 3;
    const int b_row = wn + ((b_grp & 2) ? 8 : 0) + b_r;
    const int b_kh  = (b_grp & 1) ? 8 : 0;

    int stv = 0, st2 = 2;
    for (int it = 0; it < NIT; ++it) {
        if (it + 1 < NIT) CP_WAIT1(); else CP_WAIT0();
        __syncthreads();
        if (it + 2 < NIT) ISSUE(it + 2, st2);

        const uint32_t ab = smb + (uint32_t)stv * STAGE_B;
        const uint32_t bb = smb + (uint32_t)(NSTG + stv) * STAGE_B;

        #pragma unroll
        for (int h = 0; h < 4; ++h) {
            uint32_t a[4][4];
            #pragma unroll
            for (int i = 0; i < 4; ++i)
                ldsm_x4(a[i][0], a[i][1], a[i][2], a[i][3],
                        ab + (uint32_t)((a_row + i * 16) * ROWP + h * 16 + a_kh) * 2);
            uint32_t bfr[8];
            #pragma unroll
            for (int j = 0; j < 2; ++j)
                ldsm_x4(bfr[j * 4 + 0], bfr[j * 4 + 1], bfr[j * 4 + 2], bfr[j * 4 + 3],
                        bb + (uint32_t)((b_row + j * 16) * ROWP + h * 16 + b_kh) * 2);
            #pragma unroll
            for (int i = 0; i < 4; ++i)
                #pragma unroll
                for (int jt = 0; jt < 4; ++jt)
                    mma16816(c[i][jt], a[i],
                             bfr[(jt >> 1) * 4 + (jt & 1) * 2],
                             bfr[(jt >> 1) * 4 + (jt & 1) * 2 + 1]);
        }

        stv = (stv + 1 == NSTG) ? 0 : stv + 1;
        st2 = (st2 + 1 == NSTG) ? 0 : st2 + 1;
    }
    #undef ISSUE

    // epilogue: + bias, bf16x2 stores
    const int g  = lane >> 2;
    const int tc = lane & 3;
    #pragma unroll
    for (int jt = 0; jt < 4; ++jt) {
        const int col = n0 + wn + jt * 8 + tc * 2;
        const float2 bias = *(const float2*)&b_enc[col];
        #pragma unroll
        for (int i = 0; i < 4; ++i) {
            const int r0 = m0 + wm + i * 16 + g;
            *(__nv_bfloat162*)&g_pre[(size_t)r0 * D_SAE_ + col] =
                __nv_bfloat162(__float2bfloat16_rn(c[i][jt][0] + bias.x),
                               __float2bfloat16_rn(c[i][jt][1] + bias.y));
            *(__nv_bfloat162*)&g_pre[(size_t)(r0 + 8) * D_SAE_ + col] =
                __nv_bfloat162(__float2bfloat16_rn(c[i][jt][2] + bias.x),
                               __float2bfloat16_rn(c[i][jt][3] + bias.y));
        }
    }
}

// =====================================================================
// Kernel D: candidate select — keys staged in SHARED MEMORY.
// Per-thread register state is one uint4 in flight; all phases stream
// skey[] (16 KB). hist 16 KB. Two-level (12+4 bit) threshold + compaction.
// =====================================================================
__global__ __launch_bounds__(256) void cand_select_kernel()
{
    __shared__ uint16_t skey[D_SAE_];   // 16 KB: monotonic keys
    __shared__ int hist[4096];          // 16 KB
    __shared__ int sub[16];
    __shared__ int candsm[NCAP];
    __shared__ int s_thr, s_sub, s_cnt, s_above;

    const int b = blockIdx.x;
    const int t = threadIdx.x;

    for (int i = t; i < 4096; i += 256) hist[i] = 0;
    if (t < 16) sub[t] = 0;
    if (t == 0) s_cnt = 0;

    // convert 32 bf16/thread -> keys in smem (no persistent registers)
    const uint4* rp = (const uint4*)(g_pre + (size_t)b * D_SAE_);
    #pragma unroll
    for (int q = 0; q < 4; ++q) {
        uint4 v = __ldg(&rp[t + q * 256]);
        const uint32_t* pw = (const uint32_t*)&v;
        const int base = (t + q * 256) * 8;
        #pragma unroll
        for (int d = 0; d < 4; ++d) {
            skey[base + d * 2 + 0] = (uint16_t)fkey16(pw[d] & 0xFFFFu);
            skey[base + d * 2 + 1] = (uint16_t)fkey16(pw[d] >> 16);
        }
    }
    __syncthreads();

    // histogram over top-12 key bits
    for (int i = t; i < D_SAE_; i += 256)
        atomicAdd(&hist[skey[i] >> 4], 1);
    __syncthreads();

    // level 1: 12-bit threshold bin + count strictly above
    if (t < 32) {
        int cum = 0;
        for (int c = 0; c < 128; ++c) {
            int bin = 4095 - c * 32 - t;
            int cnt = hist[bin];
            int pre = cnt;
            #pragma unroll
            for (int s = 1; s < 32; s <<= 1) {
                int o = __shfl_up_sync(0xffffffffu, pre, s);
                if (t >= s) pre += o;
            }
            int total = __shfl_sync(0xffffffffu, pre, 31);
            if (cum + total >= KCAND) {
                unsigned m = __ballot_sync(0xffffffffu, cum + pre >= KCAND);
                int fl = __ffs(m) - 1;
                if (t == fl) { s_thr = bin; s_above = cum + pre - cnt; }
                break;
            }
            cum += total;
        }
    }
    __syncthreads();
    const int thr = s_thr;
    const int need2 = KCAND - s_above;

    // level 2: 4-bit sub-histogram within boundary bin
    for (int i = t; i < D_SAE_; i += 256) {
        uint32_t k = skey[i];
        if ((int)(k >> 4) == thr) atomicAdd(&sub[k & 0xFu], 1);
    }
    __syncthreads();
    if (t == 0) {
        int cum = 0, bsel = 0;
        for (int bin = 15; bin >= 0; --bin) {
            cum += sub[bin];
            if (cum >= need2) { bsel = bin; break; }
        }
        s_sub = bsel;
    }
    __syncthreads();
    const uint32_t cutoff16 = ((uint32_t)thr << 4) | (uint32_t)s_sub;

    // compaction: strictly above (fits), then boundary (capped at NCAP)
    for (int i = t; i < D_SAE_; i += 256) {
        if ((uint32_t)skey[i] > cutoff16) {
            int p = atomicAdd(&s_cnt, 1);
            candsm[p] = i;
        }
    }
    __syncthreads();
    for (int i = t; i < D_SAE_; i += 256) {
        if ((uint32_t)skey[i] == cutoff16) {
            int p = atomicAdd(&s_cnt, 1);
            if (p < NCAP) candsm[p] = i;
        }
    }
    __syncthreads();

    int nc = min(s_cnt, NCAP);
    if (t == 0) g_cand_n[b] = nc;
    if (t < nc) g_cand[b * NCAP + t] = candsm[t];
}

// =====================================================================
// Kernel E (fused): exact fp32 rescore (per-warp full-row dots) -> exact
// top-32 -> dense z row -> sparse decode -> x_hat + loss partial
// =====================================================================
__global__ __launch_bounds__(256) void rescore_decode_kernel(
    const float* __restrict__ x,
    const float* __restrict__ Wd,
    const float* __restrict__ b_enc,
    const float* __restrict__ b_dec,
    float* __restrict__ xhat,
    float* __restrict__ z)
{
    __shared__ float xs[KDIM];
    __shared__ int   cidx[NCAP];
    __shared__ float cval[NCAP];
    __shared__ int   sidx[KTOP];
    __shared__ float sval[KTOP];
    __shared__ float wsum[8];
    __shared__ int   s_nc;

    const int b = blockIdx.x;
    const int t = threadIdx.x;
    const int lane = t & 31;
    const int w = t >> 5;

    if (t == 0) s_nc = g_cand_n[b];
    if (t < NCAP) cidx[t] = g_cand[b * NCAP + t];

    float4* xs4 = (float4*)xs;
    {
        const float4* xr4 = (const float4*)(x + (size_t)b * KDIM);
        #pragma unroll
        for (int q = 0; q < 3; ++q) xs4[t + q * 256] = __ldg(&xr4[t + q * 256]);
    }
    __syncthreads();
    const int nc = s_nc;

    for (int j = w; j < nc; j += 8) {
        const float4* wr = (const float4*)(g_Wt_f32 + (size_t)cidx[j] * KDIM);
        float s = 0.0f;
        #pragma unroll
        for (int r = 0; r < 24; ++r) {
            float4 wv = __ldg(&wr[lane + r * 32]);
            float4 xv = xs4[lane + r * 32];
            s = fmaf(xv.x, wv.x, s);
            s = fmaf(xv.y, wv.y, s);
            s = fmaf(xv.z, wv.z, s);
            s = fmaf(xv.w, wv.w, s);
        }
        #pragma unroll
        for (int sh = 16; sh > 0; sh >>= 1)
            s += __shfl_xor_sync(0xffffffffu, s, sh);
        if (lane == 0) cval[j] = s + __ldg(&b_enc[cidx[j]]);
    }
    __syncthreads();

    // exact top-32 among nc (<=96): warp 0, 3 slots/lane,
    // order by (value desc, global index asc) = jax stable top_k
    if (w == 0) {
        float v[3]; int ci[3];
        #pragma unroll
        for (int s3 = 0; s3 < 3; ++s3) {
            int j = lane + s3 * 32;
            bool ok = (j < nc);
            v[s3]  = ok ? cval[j] : -INFINITY;
            ci[s3] = ok ? cidx[j] : 0x7FFFFFFF;
        }
        for (int it = 0; it < KTOP; ++it) {
            float bv = v[0]; int bci = ci[0]; int bs = 0;
            #pragma unroll
            for (int s3 = 1; s3 < 3; ++s3)
                if (v[s3] > bv || (v[s3] == bv && ci[s3] < bci)) { bv = v[s3]; bci = ci[s3]; bs = s3; }
            float rv = bv; int rci = bci;
            #pragma unroll
            for (int sh = 16; sh > 0; sh >>= 1) {
                float ov = __shfl_xor_sync(0xffffffffu, rv, sh);
                int  oci = __shfl_xor_sync(0xffffffffu, rci, sh);
                if (ov > rv || (ov == rv && oci < rci)) { rv = ov; rci = oci; }
            }
            if (lane == 0) { sidx[it] = rci; sval[it] = rv; }
            if (bv == rv && bci == rci) { v[bs] = -INFINITY; ci[bs] = 0x7FFFFFFF; }
        }
    }
    __syncthreads();

    // dense z row
    float* zr = z + (size_t)b * D_SAE_;
    for (int i = t; i < D_SAE_; i += 256) zr[i] = 0.0f;
    __syncthreads();
    if (t < KTOP) {
        float vv = sval[t] > 0.0f ? sval[t] : 0.0f;
        sval[t] = vv;
        zr[sidx[t]] = vv;
    }
    __syncthreads();

    // sparse decode
    float acc[12];
    #pragma unroll
    for (int cI = 0; cI < 12; ++cI) acc[cI] = b_dec[t + cI * 256];

    #pragma unroll 4
    for (int j = 0; j < KTOP; ++j) {
        const float* wr = Wd + (size_t)sidx[j] * KDIM;
        float vv = sval[j];
        #pragma unroll
        for (int cI = 0; cI < 12; ++cI)
            acc[cI] = fmaf(vv, __ldg(&wr[t + cI * 256]), acc[cI]);
    }

    float* xo = xhat + (size_t)b * KDIM;
    float sq = 0.0f;
    #pragma unroll
    for (int cI = 0; cI < 12; ++cI) {
        float d = acc[cI] - xs[t + cI * 256];
        sq = fmaf(d, d, sq);
        xo[t + cI * 256] = acc[cI];
    }
    #pragma unroll
    for (int s = 16; s > 0; s >>= 1) sq += __shfl_down_sync(0xffffffffu, sq, s);
    if (lane == 0) wsum[w] = sq;
    __syncthreads();
    if (t == 0) {
        float s = 0.0f;
        #pragma unroll
        for (int q = 0; q < 8; ++q) s += wsum[q];
        g_loss_partial[b] = s;
    }
}

// =====================================================================
// Kernel F: loss finalize (separate kernel; no gpu-scope fences anywhere)
// =====================================================================
__global__ __launch_bounds__(256) void finalize_loss_kernel(float* __restrict__ out)
{
    __shared__ float sh[256];
    const int t = threadIdx.x;
    float s = 0.0f;
    #pragma unroll
    for (int i = 0; i < B_SZ / 256; ++i) s += g_loss_partial[t + i * 256];
    sh[t] = s;
    __syncthreads();
    #pragma unroll
    for (int k = 128; k > 0; k >>= 1) {
        if (t < k) sh[t] += sh[t + k];
        __syncthreads();
    }
    if (t == 0) out[0] = sh[0] / (float)(B_SZ * T_SZ);
}

// =====================================================================
// launch: inputs: x, W_enc, W_dec, b_enc, b_dec, k
// output: [loss(1)] [x_hat(1024*4*768)] [z(1024*8192)]
// (cand_select in ncu's profiled slot #4 to verify the smem-key fix)
// =====================================================================
extern "C" void kernel_launch(void* const* d_in, const int* in_sizes, int n_in,
                              void* d_out, int out_size)
{
    const float* x     = (const float*)d_in[0];
    const float* W_enc = (const float*)d_in[1];
    const float* W_dec = (const float*)d_in[2];
    const float* b_enc = (const float*)d_in[3];
    const float* b_dec = (const float*)d_in[4];

    float* out  = (float*)d_out;
    float* xhat = out + 1;
    float* z    = out + 1 + (size_t)B_SZ * KDIM;

    static int smem_set = 0;
    if (!smem_set) {
        cudaFuncSetAttribute(encode_gemm_hmma,
                             cudaFuncAttributeMaxDynamicSharedMemorySize, GSMEM);
        smem_set = 1;
    }

    convert_x_kernel<<<(B_SZ * KDIM / 4) / 256, 256>>>(x);
    transpose_w_kernel<<<dim3(KDIM / 32, D_SAE_ / 128), 256>>>(W_enc);
    encode_gemm_hmma<<<dim3(B_SZ / 128, D_SAE_ / 128), 256, GSMEM>>>(b_enc);
    cand_select_kernel<<<B_SZ, 256>>>();
    rescore_decode_kernel<<<B_SZ, 256>>>(x, W_dec, b_enc, b_dec, xhat, z);
    finalize_loss_kernel<<<1, 256>>>(out);
}

// round 17
// speedup vs baseline: 1.0074x; 1.0074x over previous
#include <cuda_runtime.h>
#include <cuda_bf16.h>
#include <cstdint>
#include <math.h>

// Problem constants
#define B_SZ   1024
#define T_SZ   4
#define D_IN_  768
#define D_SAE_ 8192
#define KTOP   32
#define KCAND  36          // minimum candidate count (superset size target)
#define NCAP   96          // candidate hard cap
#define KDIM   3072        // T*D_IN

// ---------------- static device scratch (no allocs) ----------------
__device__ __align__(1024) float         g_Wt_f32[(size_t)D_SAE_ * KDIM];   // W_enc^T fp32 (exact rescore)
__device__ __align__(1024) __nv_bfloat16 g_Wt_bf16[(size_t)D_SAE_ * KDIM];  // W_enc^T bf16 (MMA B)
__device__ __align__(1024) __nv_bfloat16 g_x_bf16[(size_t)B_SZ * KDIM];     // x bf16 (MMA A)
__device__ __align__(1024) __nv_bfloat16 g_pre[(size_t)B_SZ * D_SAE_];      // approx pre (bf16)
__device__ int   g_cand[B_SZ * NCAP];
__device__ int   g_cand_n[B_SZ];
__device__ float g_loss_partial[B_SZ];

// ---------------- PTX helpers (base ISA only: sm_80+) ----------------
__device__ __forceinline__ uint32_t smem_u32(const void* p) {
    uint32_t r;
    asm("{ .reg .u64 t; cvta.to.shared.u64 t, %1; cvt.u32.u64 %0, t; }" : "=r"(r) : "l"(p));
    return r;
}

__device__ __forceinline__ void cp_async16(uint32_t dst, const void* src) {
    asm volatile("cp.async.cg.shared.global [%0], [%1], 16;" :: "r"(dst), "l"(src));
}
#define CP_COMMIT() asm volatile("cp.async.commit_group;" ::: "memory")
#define CP_WAIT0()  asm volatile("cp.async.wait_group 0;" ::: "memory")
#define CP_WAIT1()  asm volatile("cp.async.wait_group 1;" ::: "memory")

__device__ __forceinline__ void ldsm_x4(uint32_t& r0, uint32_t& r1, uint32_t& r2, uint32_t& r3,
                                        uint32_t addr) {
    asm volatile("ldmatrix.sync.aligned.m8n8.x4.shared.b16 {%0,%1,%2,%3}, [%4];"
                 : "=r"(r0), "=r"(r1), "=r"(r2), "=r"(r3) : "r"(addr));
}

__device__ __forceinline__ void mma16816(float* c, const uint32_t* a, uint32_t b0, uint32_t b1) {
    asm volatile(
        "mma.sync.aligned.m16n8k16.row.col.f32.bf16.bf16.f32 "
        "{%0,%1,%2,%3}, {%4,%5,%6,%7}, {%8,%9}, {%0,%1,%2,%3};"
        : "+f"(c[0]), "+f"(c[1]), "+f"(c[2]), "+f"(c[3])
        : "r"(a[0]), "r"(a[1]), "r"(a[2]), "r"(a[3]), "r"(b0), "r"(b1));
}

// monotonic bf16-bits -> 16-bit key (total order preserved)
__device__ __forceinline__ uint32_t fkey16(uint32_t h) {
    return (h & 0x8000u) ? (~h & 0xFFFFu) : (h | 0x8000u);
}

// =====================================================================
// Kernel A: x fp32 -> bf16 (forked onto side stream, overlaps transpose)
// =====================================================================
__global__ __launch_bounds__(256) void convert_x_kernel(const float* __restrict__ x)
{
    int i = blockIdx.x * 256 + threadIdx.x;          // over 786432 float4s
    float4 v = ((const float4*)x)[i];
    __nv_bfloat162* o = (__nv_bfloat162*)g_x_bf16;
    o[i * 2 + 0] = __nv_bfloat162(__float2bfloat16_rn(v.x), __float2bfloat16_rn(v.y));
    o[i * 2 + 1] = __nv_bfloat162(__float2bfloat16_rn(v.z), __float2bfloat16_rn(v.w));
}

// =====================================================================
// Kernel B: transpose W_enc (3072,8192) -> Wt (8192,3072) fp32 + bf16
// =====================================================================
__global__ __launch_bounds__(256) void transpose_w_kernel(const float* __restrict__ W)
{
    __shared__ float s[32][129];
    const int k0 = blockIdx.x * 32;
    const int n0 = blockIdx.y * 128;
    const int t = threadIdx.x;

    {
        const int rr = t >> 5;
        const int c4 = t & 31;
        #pragma unroll
        for (int p = 0; p < 4; ++p) {
            const int kr = p * 8 + rr;
            float4 v = *(const float4*)&W[(size_t)(k0 + kr) * D_SAE_ + n0 + c4 * 4];
            s[kr][c4 * 4 + 0] = v.x;
            s[kr][c4 * 4 + 1] = v.y;
            s[kr][c4 * 4 + 2] = v.z;
            s[kr][c4 * 4 + 3] = v.w;
        }
    }
    __syncthreads();

    {
        const int nr = t >> 1;
        const int kb = (t & 1) * 16;
        float vals[16];
        #pragma unroll
        for (int i = 0; i < 16; ++i) vals[i] = s[kb + i][nr];

        float* wf = g_Wt_f32 + (size_t)(n0 + nr) * KDIM + k0 + kb;
        #pragma unroll
        for (int i4 = 0; i4 < 4; ++i4)
            *(float4*)(wf + i4 * 4) =
                make_float4(vals[i4 * 4], vals[i4 * 4 + 1], vals[i4 * 4 + 2], vals[i4 * 4 + 3]);

        __nv_bfloat162 bb[8];
        #pragma unroll
        for (int i = 0; i < 8; ++i)
            bb[i] = __nv_bfloat162(__float2bfloat16_rn(vals[i * 2]),
                                   __float2bfloat16_rn(vals[i * 2 + 1]));
        uint4* wb = (uint4*)(g_Wt_bf16 + (size_t)(n0 + nr) * KDIM + k0 + kb);
        wb[0] = *(uint4*)&bb[0];
        wb[1] = *(uint4*)&bb[4];
    }
}

// =====================================================================
// Kernel C: bf16 HMMA GEMM  g_pre(bf16) = x_bf16 @ Wt_bf16^T + b_enc
// CTA 128x128, 8 warps (2x4), warp tile 64x32. K-chunk 64, NSTG=3,
// wait->sync->issue pipeline, 2 CTAs/SM. (round-8 proven config)
// =====================================================================
#define BKT  64
#define NIT  (KDIM / BKT)      // 48
#define ROWP 72                // padded row length in bf16 elems (144 B rows)
#define STAGE_B (128 * ROWP * 2)   // 18432 bytes per operand per stage
#define NSTG 3
#define GSMEM   (2 * NSTG * STAGE_B)   // 110592 bytes

__global__ __launch_bounds__(256, 2) void encode_gemm_hmma(const float* __restrict__ b_enc)
{
    extern __shared__ __nv_bfloat16 smdyn[];

    const int tid  = threadIdx.x;
    const int wid  = tid >> 5, lane = tid & 31;
    const int m0 = blockIdx.x * 128;     // m fastest
    const int n0 = blockIdx.y * 128;
    const int wm = (wid >> 2) * 64;
    const int wn = (wid & 3) * 32;

    const uint32_t smb = smem_u32(smdyn);
    const __nv_bfloat16* __restrict__ Abf = g_x_bf16;
    const __nv_bfloat16* __restrict__ Bbf = g_Wt_bf16;

    #define ISSUE(itc, st) do {                                                           \
        int _k0 = (itc) * BKT;                                                            \
        uint32_t _ab = smb + (uint32_t)(st) * STAGE_B;                                    \
        uint32_t _bb = smb + (uint32_t)(NSTG + (st)) * STAGE_B;                           \
        _Pragma("unroll")                                                                 \
        for (int q = 0; q < 4; ++q) {                                                     \
            int u = tid + q * 256, row = u >> 3, seg = u & 7;                             \
            uint32_t doff = (uint32_t)(row * ROWP + seg * 8) * 2;                         \
            cp_async16(_ab + doff, Abf + (size_t)(m0 + row) * KDIM + _k0 + seg * 8);      \
            cp_async16(_bb + doff, Bbf + (size_t)(n0 + row) * KDIM + _k0 + seg * 8);      \
        }                                                                                 \
        CP_COMMIT();                                                                      \
    } while (0)

    float c[4][4][4];
    #pragma unroll
    for (int i = 0; i < 4; ++i)
        #pragma unroll
        for (int j = 0; j < 4; ++j)
            #pragma unroll
            for (int q = 0; q < 4; ++q) c[i][j][q] = 0.0f;

    ISSUE(0, 0);
    ISSUE(1, 1);

    const int a_row = wm + (lane & 15);
    const int a_kh  = (lane >> 4) * 8;
    const int b_r   = lane & 7;
    const int b_grp = lane >> 3;
    const int b_row = wn + ((b_grp & 2) ? 8 : 0) + b_r;
    const int b_kh  = (b_grp & 1) ? 8 : 0;

    int stv = 0, st2 = 2;
    for (int it = 0; it < NIT; ++it) {
        if (it + 1 < NIT) CP_WAIT1(); else CP_WAIT0();
        __syncthreads();
        if (it + 2 < NIT) ISSUE(it + 2, st2);

        const uint32_t ab = smb + (uint32_t)stv * STAGE_B;
        const uint32_t bb = smb + (uint32_t)(NSTG + stv) * STAGE_B;

        #pragma unroll
        for (int h = 0; h < 4; ++h) {
            uint32_t a[4][4];
            #pragma unroll
            for (int i = 0; i < 4; ++i)
                ldsm_x4(a[i][0], a[i][1], a[i][2], a[i][3],
                        ab + (uint32_t)((a_row + i * 16) * ROWP + h * 16 + a_kh) * 2);
            uint32_t bfr[8];
            #pragma unroll
            for (int j = 0; j < 2; ++j)
                ldsm_x4(bfr[j * 4 + 0], bfr[j * 4 + 1], bfr[j * 4 + 2], bfr[j * 4 + 3],
                        bb + (uint32_t)((b_row + j * 16) * ROWP + h * 16 + b_kh) * 2);
            #pragma unroll
            for (int i = 0; i < 4; ++i)
                #pragma unroll
                for (int jt = 0; jt < 4; ++jt)
                    mma16816(c[i][jt], a[i],
                             bfr[(jt >> 1) * 4 + (jt & 1) * 2],
                             bfr[(jt >> 1) * 4 + (jt & 1) * 2 + 1]);
        }

        stv = (stv + 1 == NSTG) ? 0 : stv + 1;
        st2 = (st2 + 1 == NSTG) ? 0 : st2 + 1;
    }
    #undef ISSUE

    // epilogue: + bias, bf16x2 stores
    const int g  = lane >> 2;
    const int tc = lane & 3;
    #pragma unroll
    for (int jt = 0; jt < 4; ++jt) {
        const int col = n0 + wn + jt * 8 + tc * 2;
        const float2 bias = *(const float2*)&b_enc[col];
        #pragma unroll
        for (int i = 0; i < 4; ++i) {
            const int r0 = m0 + wm + i * 16 + g;
            *(__nv_bfloat162*)&g_pre[(size_t)r0 * D_SAE_ + col] =
                __nv_bfloat162(__float2bfloat16_rn(c[i][jt][0] + bias.x),
                               __float2bfloat16_rn(c[i][jt][1] + bias.y));
            *(__nv_bfloat162*)&g_pre[(size_t)(r0 + 8) * D_SAE_ + col] =
                __nv_bfloat162(__float2bfloat16_rn(c[i][jt][2] + bias.x),
                               __float2bfloat16_rn(c[i][jt][3] + bias.y));
        }
    }
}

// =====================================================================
// Kernel D: candidate select — keys staged in SHARED MEMORY.
// Keygen + histogram fused into one sweep (saves a full pass).
// Two-level (12+4 bit) threshold; compaction. Low-reg (~34).
// =====================================================================
__global__ __launch_bounds__(256) void cand_select_kernel()
{
    __shared__ uint16_t skey[D_SAE_];   // 16 KB: monotonic keys
    __shared__ int hist[4096];          // 16 KB
    __shared__ int sub[16];
    __shared__ int candsm[NCAP];
    __shared__ int s_thr, s_sub, s_cnt, s_above;

    const int b = blockIdx.x;
    const int t = threadIdx.x;

    for (int i = t; i < 4096; i += 256) hist[i] = 0;
    if (t < 16) sub[t] = 0;
    if (t == 0) s_cnt = 0;
    __syncthreads();   // hist zeroed before fused keygen+histogram

    // fused: convert 32 bf16/thread -> keys in smem AND histogram them
    const uint4* rp = (const uint4*)(g_pre + (size_t)b * D_SAE_);
    #pragma unroll
    for (int q = 0; q < 4; ++q) {
        uint4 v = __ldg(&rp[t + q * 256]);
        const uint32_t* pw = (const uint32_t*)&v;
        const int base = (t + q * 256) * 8;
        #pragma unroll
        for (int d = 0; d < 4; ++d) {
            uint32_t k0v = fkey16(pw[d] & 0xFFFFu);
            uint32_t k1v = fkey16(pw[d] >> 16);
            skey[base + d * 2 + 0] = (uint16_t)k0v;
            skey[base + d * 2 + 1] = (uint16_t)k1v;
            atomicAdd(&hist[k0v >> 4], 1);
            atomicAdd(&hist[k1v >> 4], 1);
        }
    }
    __syncthreads();

    // level 1: 12-bit threshold bin + count strictly above
    if (t < 32) {
        int cum = 0;
        for (int c = 0; c < 128; ++c) {
            int bin = 4095 - c * 32 - t;
            int cnt = hist[bin];
            int pre = cnt;
            #pragma unroll
            for (int s = 1; s < 32; s <<= 1) {
                int o = __shfl_up_sync(0xffffffffu, pre, s);
                if (t >= s) pre += o;
            }
            int total = __shfl_sync(0xffffffffu, pre, 31);
            if (cum + total >= KCAND) {
                unsigned m = __ballot_sync(0xffffffffu, cum + pre >= KCAND);
                int fl = __ffs(m) - 1;
                if (t == fl) { s_thr = bin; s_above = cum + pre - cnt; }
                break;
            }
            cum += total;
        }
    }
    __syncthreads();
    const int thr = s_thr;
    const int need2 = KCAND - s_above;

    // level 2: 4-bit sub-histogram within boundary bin
    for (int i = t; i < D_SAE_; i += 256) {
        uint32_t k = skey[i];
        if ((int)(k >> 4) == thr) atomicAdd(&sub[k & 0xFu], 1);
    }
    __syncthreads();
    if (t == 0) {
        int cum = 0, bsel = 0;
        for (int bin = 15; bin >= 0; --bin) {
            cum += sub[bin];
            if (cum >= need2) { bsel = bin; break; }
        }
        s_sub = bsel;
    }
    __syncthreads();
    const uint32_t cutoff16 = ((uint32_t)thr << 4) | (uint32_t)s_sub;

    // compaction: strictly above (fits), then boundary (capped at NCAP)
    for (int i = t; i < D_SAE_; i += 256) {
        if ((uint32_t)skey[i] > cutoff16) {
            int p = atomicAdd(&s_cnt, 1);
            candsm[p] = i;
        }
    }
    __syncthreads();
    for (int i = t; i < D_SAE_; i += 256) {
        if ((uint32_t)skey[i] == cutoff16) {
            int p = atomicAdd(&s_cnt, 1);
            if (p < NCAP) candsm[p] = i;
        }
    }
    __syncthreads();

    int nc = min(s_cnt, NCAP);
    if (t == 0) g_cand_n[b] = nc;
    if (t < nc) g_cand[b * NCAP + t] = candsm[t];
}

// =====================================================================
// Kernel E (fused): exact fp32 rescore (per-warp full-row dots) -> exact
// top-32 -> dense z row -> sparse decode -> x_hat + loss partial
// =====================================================================
__global__ __launch_bounds__(256) void rescore_decode_kernel(
    const float* __restrict__ x,
    const float* __restrict__ Wd,
    const float* __restrict__ b_enc,
    const float* __restrict__ b_dec,
    float* __restrict__ xhat,
    float* __restrict__ z)
{
    __shared__ float xs[KDIM];
    __shared__ int   cidx[NCAP];
    __shared__ float cval[NCAP];
    __shared__ int   sidx[KTOP];
    __shared__ float sval[KTOP];
    __shared__ float wsum[8];
    __shared__ int   s_nc;

    const int b = blockIdx.x;
    const int t = threadIdx.x;
    const int lane = t & 31;
    const int w = t >> 5;

    if (t == 0) s_nc = g_cand_n[b];
    if (t < NCAP) cidx[t] = g_cand[b * NCAP + t];

    float4* xs4 = (float4*)xs;
    {
        const float4* xr4 = (const float4*)(x + (size_t)b * KDIM);
        #pragma unroll
        for (int q = 0; q < 3; ++q) xs4[t + q * 256] = __ldg(&xr4[t + q * 256]);
    }
    __syncthreads();
    const int nc = s_nc;

    for (int j = w; j < nc; j += 8) {
        const float4* wr = (const float4*)(g_Wt_f32 + (size_t)cidx[j] * KDIM);
        float s = 0.0f;
        #pragma unroll
        for (int r = 0; r < 24; ++r) {
            float4 wv = __ldg(&wr[lane + r * 32]);
            float4 xv = xs4[lane + r * 32];
            s = fmaf(xv.x, wv.x, s);
            s = fmaf(xv.y, wv.y, s);
            s = fmaf(xv.z, wv.z, s);
            s = fmaf(xv.w, wv.w, s);
        }
        #pragma unroll
        for (int sh = 16; sh > 0; sh >>= 1)
            s += __shfl_xor_sync(0xffffffffu, s, sh);
        if (lane == 0) cval[j] = s + __ldg(&b_enc[cidx[j]]);
    }
    __syncthreads();

    // exact top-32 among nc (<=96): warp 0, 3 slots/lane,
    // order by (value desc, global index asc) = jax stable top_k
    if (w == 0) {
        float v[3]; int ci[3];
        #pragma unroll
        for (int s3 = 0; s3 < 3; ++s3) {
            int j = lane + s3 * 32;
            bool ok = (j < nc);
            v[s3]  = ok ? cval[j] : -INFINITY;
            ci[s3] = ok ? cidx[j] : 0x7FFFFFFF;
        }
        for (int it = 0; it < KTOP; ++it) {
            float bv = v[0]; int bci = ci[0]; int bs = 0;
            #pragma unroll
            for (int s3 = 1; s3 < 3; ++s3)
                if (v[s3] > bv || (v[s3] == bv && ci[s3] < bci)) { bv = v[s3]; bci = ci[s3]; bs = s3; }
            float rv = bv; int rci = bci;
            #pragma unroll
            for (int sh = 16; sh > 0; sh >>= 1) {
                float ov = __shfl_xor_sync(0xffffffffu, rv, sh);
                int  oci = __shfl_xor_sync(0xffffffffu, rci, sh);
                if (ov > rv || (ov == rv && oci < rci)) { rv = ov; rci = oci; }
            }
            if (lane == 0) { sidx[it] = rci; sval[it] = rv; }
            if (bv == rv && bci == rci) { v[bs] = -INFINITY; ci[bs] = 0x7FFFFFFF; }
        }
    }
    __syncthreads();

    // dense z row
    float* zr = z + (size_t)b * D_SAE_;
    for (int i = t; i < D_SAE_; i += 256) zr[i] = 0.0f;
    __syncthreads();
    if (t < KTOP) {
        float vv = sval[t] > 0.0f ? sval[t] : 0.0f;
        sval[t] = vv;
        zr[sidx[t]] = vv;
    }
    __syncthreads();

    // sparse decode
    float acc[12];
    #pragma unroll
    for (int cI = 0; cI < 12; ++cI) acc[cI] = b_dec[t + cI * 256];

    #pragma unroll 4
    for (int j = 0; j < KTOP; ++j) {
        const float* wr = Wd + (size_t)sidx[j] * KDIM;
        float vv = sval[j];
        #pragma unroll
        for (int cI = 0; cI < 12; ++cI)
            acc[cI] = fmaf(vv, __ldg(&wr[t + cI * 256]), acc[cI]);
    }

    float* xo = xhat + (size_t)b * KDIM;
    float sq = 0.0f;
    #pragma unroll
    for (int cI = 0; cI < 12; ++cI) {
        float d = acc[cI] - xs[t + cI * 256];
        sq = fmaf(d, d, sq);
        xo[t + cI * 256] = acc[cI];
    }
    #pragma unroll
    for (int s = 16; s > 0; s >>= 1) sq += __shfl_down_sync(0xffffffffu, sq, s);
    if (lane == 0) wsum[w] = sq;
    __syncthreads();
    if (t == 0) {
        float s = 0.0f;
        #pragma unroll
        for (int q = 0; q < 8; ++q) s += wsum[q];
        g_loss_partial[b] = s;
    }
}

// =====================================================================
// Kernel F: loss finalize
// =====================================================================
__global__ __launch_bounds__(256) void finalize_loss_kernel(float* __restrict__ out)
{
    __shared__ float sh[256];
    const int t = threadIdx.x;
    float s = 0.0f;
    #pragma unroll
    for (int i = 0; i < B_SZ / 256; ++i) s += g_loss_partial[t + i * 256];
    sh[t] = s;
    __syncthreads();
    #pragma unroll
    for (int k = 128; k > 0; k >>= 1) {
        if (t < k) sh[t] += sh[t + k];
        __syncthreads();
    }
    if (t == 0) out[0] = sh[0] / (float)(B_SZ * T_SZ);
}

// =====================================================================
// launch: inputs: x, W_enc, W_dec, b_enc, b_dec, k
// output: [loss(1)] [x_hat(1024*4*768)] [z(1024*8192)]
// Stream fork: convert_x (24 MB) overlaps transpose (251 MB) — disjoint
// traffic, both DRAM-bound, sum under the DRAM roof. Join before GEMM.
// =====================================================================
extern "C" void kernel_launch(void* const* d_in, const int* in_sizes, int n_in,
                              void* d_out, int out_size)
{
    const float* x     = (const float*)d_in[0];
    const float* W_enc = (const float*)d_in[1];
    const float* W_dec = (const float*)d_in[2];
    const float* b_enc = (const float*)d_in[3];
    const float* b_dec = (const float*)d_in[4];

    float* out  = (float*)d_out;
    float* xhat = out + 1;
    float* z    = out + 1 + (size_t)B_SZ * KDIM;

    static bool init_done = false;
    static cudaStream_t s1 = 0;
    static cudaEvent_t evF = 0, evC = 0;
    if (!init_done) {
        init_done = true;
        cudaFuncSetAttribute(encode_gemm_hmma,
                             cudaFuncAttributeMaxDynamicSharedMemorySize, GSMEM);
        if (cudaStreamCreateWithFlags(&s1, cudaStreamNonBlocking) != cudaSuccess) {
            s1 = 0;
        } else if (cudaEventCreateWithFlags(&evF, cudaEventDisableTiming) != cudaSuccess ||
                   cudaEventCreateWithFlags(&evC, cudaEventDisableTiming) != cudaSuccess) {
            s1 = 0;
        }
    }

    const dim3 gtrans(KDIM / 32, D_SAE_ / 128);
    const dim3 ggemm(B_SZ / 128, D_SAE_ / 128);

    if (s1) {
        cudaEventRecord(evF, 0);
        cudaStreamWaitEvent(s1, evF, 0);
        convert_x_kernel<<<(B_SZ * KDIM / 4) / 256, 256, 0, s1>>>(x);   // side stream
        cudaEventRecord(evC, s1);
        transpose_w_kernel<<<gtrans, 256>>>(W_enc);                     // main stream
        cudaStreamWaitEvent(0, evC, 0);                                 // join before GEMM
        encode_gemm_hmma<<<ggemm, 256, GSMEM>>>(b_enc);
    } else {
        convert_x_kernel<<<(B_SZ * KDIM / 4) / 256, 256>>>(x);
        transpose_w_kernel<<<gtrans, 256>>>(W_enc);
        encode_gemm_hmma<<<ggemm, 256, GSMEM>>>(b_enc);
    }
    cand_select_kernel<<<B_SZ, 256>>>();
    rescore_decode_kernel<<<B_SZ, 256>>>(x, W_dec, b_enc, b_dec, xhat, z);
    finalize_loss_kernel<<<1, 256>>>(out);
}